// round 1
// baseline (speedup 1.0000x reference)
#include <cuda_runtime.h>
#include <math.h>
#include <stdint.h>

#define S_LEN 1024
#define BATCH 2
#define HDIM  1024
#define EDIM  512
#define VDIM  32000
#define MDIM  128

// ---------------- scratch (device globals; no allocations) ----------------
__device__ float g_xg[BATCH * S_LEN * 3 * HDIM];     // 25.2 MB
__device__ float g_states[BATCH * S_LEN * HDIM];     // 8.4 MB
__device__ float g_ns[BATCH * S_LEN * HDIM];         // 8.4 MB
__device__ float g_hf[BATCH * S_LEN * 4 * EDIM];     // 16.8 MB
__device__ float g_base[BATCH * S_LEN * EDIM];       // 4.2 MB
__device__ float g_q[BATCH * S_LEN * MDIM];
__device__ float g_k[BATCH * S_LEN * MDIM];
__device__ float g_gate[BATCH * S_LEN];
__device__ float g_hbuf[2 * BATCH * HDIM];           // ping-pong h
__device__ unsigned int g_bar;

// ---------------- init (reset barrier + h0 every replay) ----------------
__global__ void init_kernel() {
    int t = blockIdx.x * blockDim.x + threadIdx.x;
    if (t == 0) g_bar = 0u;
    if (t < 2 * BATCH * HDIM) g_hbuf[t] = 0.f;
}

// ---------------- generic C[M,N] = A[M,K] @ B[N,K]^T + bias ----------------
// EPI: 0 = bias only, 1 = squared-relu(bias add first)
template <int EPI, bool GATHER>
__global__ void __launch_bounds__(256, 2) sgemm_tn(
    const float* __restrict__ A, const float* __restrict__ Bm,
    const float* __restrict__ bias, float* __restrict__ C,
    int M, int N, int K, const int* __restrict__ gidx)
{
    __shared__ float As[8][132];
    __shared__ float Bs[8][132];
    const int tid = threadIdx.x;
    const int tx = tid & 15, ty = tid >> 4;
    const int lr = tid >> 1;
    const int lc = (tid & 1) * 4;
    int arow = blockIdx.y * 128 + lr;
    if (GATHER) arow = gidx[arow];
    const float* Ap = A + (size_t)arow * K + lc;
    const float* Bp = Bm + (size_t)(blockIdx.x * 128 + lr) * K + lc;

    float acc[8][8];
#pragma unroll
    for (int i = 0; i < 8; i++)
#pragma unroll
        for (int j = 0; j < 8; j++) acc[i][j] = 0.f;

    for (int k0 = 0; k0 < K; k0 += 8) {
        float4 av = *(const float4*)(Ap + k0);
        float4 bv = *(const float4*)(Bp + k0);
        As[lc + 0][lr] = av.x; As[lc + 1][lr] = av.y;
        As[lc + 2][lr] = av.z; As[lc + 3][lr] = av.w;
        Bs[lc + 0][lr] = bv.x; Bs[lc + 1][lr] = bv.y;
        Bs[lc + 2][lr] = bv.z; Bs[lc + 3][lr] = bv.w;
        __syncthreads();
#pragma unroll
        for (int kk = 0; kk < 8; kk++) {
            float4 a0 = *(const float4*)&As[kk][ty * 8];
            float4 a1 = *(const float4*)&As[kk][ty * 8 + 4];
            float4 b0 = *(const float4*)&Bs[kk][tx * 8];
            float4 b1 = *(const float4*)&Bs[kk][tx * 8 + 4];
            float ar[8] = {a0.x, a0.y, a0.z, a0.w, a1.x, a1.y, a1.z, a1.w};
            float br[8] = {b0.x, b0.y, b0.z, b0.w, b1.x, b1.y, b1.z, b1.w};
#pragma unroll
            for (int i = 0; i < 8; i++)
#pragma unroll
                for (int j = 0; j < 8; j++)
                    acc[i][j] = fmaf(ar[i], br[j], acc[i][j]);
        }
        __syncthreads();
    }

    const int cc = blockIdx.x * 128 + tx * 8;
    float bl[8];
#pragma unroll
    for (int j = 0; j < 8; j++) bl[j] = bias[cc + j];
#pragma unroll
    for (int i = 0; i < 8; i++) {
        int row = blockIdx.y * 128 + ty * 8 + i;
        float v[8];
#pragma unroll
        for (int j = 0; j < 8; j++) {
            float x = acc[i][j] + bl[j];
            if (EPI == 1) { x = fmaxf(x, 0.f); x = x * x; }
            v[j] = x;
        }
        float4* Cp = (float4*)(C + (size_t)row * N + cc);
        Cp[0] = make_float4(v[0], v[1], v[2], v[3]);
        Cp[1] = make_float4(v[4], v[5], v[6], v[7]);
    }
}

// ---------------- GRU: persistent, 128 CTAs x 256 thr, weights in regs ----
__global__ void __launch_bounds__(256, 1) gru_kernel(
    const float* __restrict__ xg, const float* __restrict__ w_hh,
    const float* __restrict__ b_hh, float* __restrict__ states)
{
    __shared__ float hsh[2 * HDIM];
    __shared__ float dres[8][3][2];
    __shared__ float bsh[3][8];
    const int tid = threadIdx.x;
    const int w = tid >> 5, l = tid & 31;
    const int jbase = blockIdx.x * 8;

    // per-warp: 3 gate rows of w_hh for hidden dim (jbase + w), register-resident
    float4 wreg[3][8];
#pragma unroll
    for (int g = 0; g < 3; g++) {
        const float* wr = w_hh + (size_t)(g * HDIM + jbase + w) * HDIM + l * 4;
#pragma unroll
        for (int u = 0; u < 8; u++)
            wreg[g][u] = *(const float4*)(wr + u * 128);
    }
    if (tid < 24) bsh[tid >> 3][tid & 7] = b_hh[(tid >> 3) * HDIM + jbase + (tid & 7)];

    const unsigned G = gridDim.x;
    for (int t = 0; t < S_LEN; t++) {
        const int p = t & 1;
        // stage full h (both batches) into smem, L1-bypassed
        {
            const float4* hs = (const float4*)(g_hbuf + p * (2 * HDIM));
            float4* hd = (float4*)hsh;
            hd[tid]       = __ldcg(hs + tid);
            hd[tid + 256] = __ldcg(hs + tid + 256);
        }
        // prefetch this step's xg for the 16 combiner threads
        float xr = 0.f, xz = 0.f, xn = 0.f;
        if (tid < 16) {
            const int b = tid >> 3, j2 = tid & 7;
            const float* xp = xg + (size_t)(b * S_LEN + t) * (3 * HDIM) + jbase + j2;
            xr = xp[0]; xz = xp[HDIM]; xn = xp[2 * HDIM];
        }
        __syncthreads();

        // 6 dot products per warp (3 gates x 2 batches), K split over lanes
        float a00 = 0.f, a01 = 0.f, a10 = 0.f, a11 = 0.f, a20 = 0.f, a21 = 0.f;
#pragma unroll
        for (int u = 0; u < 8; u++) {
            float4 h0 = *(const float4*)&hsh[u * 128 + l * 4];
            float4 h1 = *(const float4*)&hsh[HDIM + u * 128 + l * 4];
            float4 w0 = wreg[0][u], w1 = wreg[1][u], w2 = wreg[2][u];
            a00 += w0.x * h0.x + w0.y * h0.y + w0.z * h0.z + w0.w * h0.w;
            a01 += w0.x * h1.x + w0.y * h1.y + w0.z * h1.z + w0.w * h1.w;
            a10 += w1.x * h0.x + w1.y * h0.y + w1.z * h0.z + w1.w * h0.w;
            a11 += w1.x * h1.x + w1.y * h1.y + w1.z * h1.z + w1.w * h1.w;
            a20 += w2.x * h0.x + w2.y * h0.y + w2.z * h0.z + w2.w * h0.w;
            a21 += w2.x * h1.x + w2.y * h1.y + w2.z * h1.z + w2.w * h1.w;
        }
#pragma unroll
        for (int off = 16; off > 0; off >>= 1) {
            a00 += __shfl_xor_sync(0xffffffffu, a00, off);
            a01 += __shfl_xor_sync(0xffffffffu, a01, off);
            a10 += __shfl_xor_sync(0xffffffffu, a10, off);
            a11 += __shfl_xor_sync(0xffffffffu, a11, off);
            a20 += __shfl_xor_sync(0xffffffffu, a20, off);
            a21 += __shfl_xor_sync(0xffffffffu, a21, off);
        }
        if (l == 0) {
            dres[w][0][0] = a00; dres[w][0][1] = a01;
            dres[w][1][0] = a10; dres[w][1][1] = a11;
            dres[w][2][0] = a20; dres[w][2][1] = a21;
        }
        __syncthreads();

        if (tid < 16) {
            const int b = tid >> 3, j2 = tid & 7;
            float hr = dres[j2][0][b] + bsh[0][j2];
            float hz = dres[j2][1][b] + bsh[1][j2];
            float hn = dres[j2][2][b] + bsh[2][j2];
            float r = 1.f / (1.f + expf(-(xr + hr)));
            float z = 1.f / (1.f + expf(-(xz + hz)));
            float n = tanhf(xn + r * hn);
            float hold = hsh[b * HDIM + jbase + j2];
            float hnew = (1.f - z) * n + z * hold;
            __stcg(&g_hbuf[(p ^ 1) * (2 * HDIM) + b * HDIM + jbase + j2], hnew);
            states[(size_t)(b * S_LEN + t) * HDIM + jbase + j2] = hnew;
        }
        __syncthreads();

        // global barrier: release h writes, wait for all CTAs
        if (tid == 0) {
            __threadfence();
            atomicAdd(&g_bar, 1u);
            const unsigned target = (unsigned)(t + 1) * G;
            while (*((volatile unsigned*)&g_bar) < target) { }
            __threadfence();
        }
        __syncthreads();
    }
}

// ---------------- LayerNorm + gate (fused per-row) ----------------
__global__ void __launch_bounds__(256) ln_gate_kernel(
    const float* __restrict__ states, const float* __restrict__ ln_g,
    const float* __restrict__ ln_b, const float* __restrict__ wg,
    const float* __restrict__ bg, float* __restrict__ ns, float* __restrict__ gate)
{
    __shared__ float red[3][8];
    const int row = blockIdx.x;
    const int tid = threadIdx.x;
    const float4 xv = ((const float4*)(states + (size_t)row * HDIM))[tid];
    const float4 wv = ((const float4*)wg)[tid];
    float s  = xv.x + xv.y + xv.z + xv.w;
    float sq = xv.x * xv.x + xv.y * xv.y + xv.z * xv.z + xv.w * xv.w;
    float wd = xv.x * wv.x + xv.y * wv.y + xv.z * wv.z + xv.w * wv.w;
#pragma unroll
    for (int off = 16; off > 0; off >>= 1) {
        s  += __shfl_xor_sync(0xffffffffu, s,  off);
        sq += __shfl_xor_sync(0xffffffffu, sq, off);
        wd += __shfl_xor_sync(0xffffffffu, wd, off);
    }
    if ((tid & 31) == 0) { red[0][tid >> 5] = s; red[1][tid >> 5] = sq; red[2][tid >> 5] = wd; }
    __syncthreads();
    s = 0.f; sq = 0.f; wd = 0.f;
#pragma unroll
    for (int u = 0; u < 8; u++) { s += red[0][u]; sq += red[1][u]; wd += red[2][u]; }
    const float mu = s * (1.f / HDIM);
    const float var = sq * (1.f / HDIM) - mu * mu;
    const float rstd = rsqrtf(var + 1e-5f);
    const float4 gv = ((const float4*)ln_g)[tid];
    const float4 bv = ((const float4*)ln_b)[tid];
    float4 o;
    o.x = (xv.x - mu) * rstd * gv.x + bv.x;
    o.y = (xv.y - mu) * rstd * gv.y + bv.y;
    o.z = (xv.z - mu) * rstd * gv.z + bv.z;
    o.w = (xv.w - mu) * rstd * gv.w + bv.w;
    ((float4*)(ns + (size_t)row * HDIM))[tid] = o;
    if (tid == 0) gate[row] = 1.f / (1.f + expf(-(wd + bg[0])));
}

// ---------------- q/k projection: 16-row x 128-col tiles ----------------
__global__ void __launch_bounds__(256) qk_kernel(
    const float* __restrict__ states,
    const float* __restrict__ wq, const float* __restrict__ bq,
    const float* __restrict__ wk, const float* __restrict__ bk,
    float* __restrict__ qout, float* __restrict__ kout)
{
    const float* W    = blockIdx.y ? wk : wq;
    const float* bias = blockIdx.y ? bk : bq;
    float* out        = blockIdx.y ? kout : qout;
    __shared__ float As[16][20];
    __shared__ float Ws[16][128];
    const int tid = threadIdx.x;
    const int m0 = blockIdx.x * 16;
    const int tm = tid >> 4;
    const int tn0 = (tid & 15) * 8;
    float acc[8] = {0.f, 0.f, 0.f, 0.f, 0.f, 0.f, 0.f, 0.f};

    for (int k0 = 0; k0 < HDIM; k0 += 16) {
        {
            const int n = tid >> 1;
            const int ks = (tid & 1) * 8;
            const float* wp = W + (size_t)n * HDIM + k0 + ks;
            float4 w0 = *(const float4*)wp;
            float4 w1 = *(const float4*)(wp + 4);
            Ws[ks + 0][n] = w0.x; Ws[ks + 1][n] = w0.y; Ws[ks + 2][n] = w0.z; Ws[ks + 3][n] = w0.w;
            Ws[ks + 4][n] = w1.x; Ws[ks + 5][n] = w1.y; Ws[ks + 6][n] = w1.z; Ws[ks + 7][n] = w1.w;
        }
        if (tid < 64) {
            const int m = tid >> 2;
            const int ks = (tid & 3) * 4;
            float4 a = *(const float4*)(states + (size_t)(m0 + m) * HDIM + k0 + ks);
            As[m][ks] = a.x; As[m][ks + 1] = a.y; As[m][ks + 2] = a.z; As[m][ks + 3] = a.w;
        }
        __syncthreads();
#pragma unroll
        for (int kk = 0; kk < 16; kk++) {
            float a = As[tm][kk];
            float4 b0 = *(const float4*)&Ws[kk][tn0];
            float4 b1 = *(const float4*)&Ws[kk][tn0 + 4];
            acc[0] += a * b0.x; acc[1] += a * b0.y; acc[2] += a * b0.z; acc[3] += a * b0.w;
            acc[4] += a * b1.x; acc[5] += a * b1.y; acc[6] += a * b1.z; acc[7] += a * b1.w;
        }
        __syncthreads();
    }
    float4 o0 = make_float4(acc[0] + bias[tn0 + 0], acc[1] + bias[tn0 + 1],
                            acc[2] + bias[tn0 + 2], acc[3] + bias[tn0 + 3]);
    float4 o1 = make_float4(acc[4] + bias[tn0 + 4], acc[5] + bias[tn0 + 5],
                            acc[6] + bias[tn0 + 6], acc[7] + bias[tn0 + 7]);
    float4* op = (float4*)(out + (size_t)(m0 + tm) * MDIM + tn0);
    op[0] = o0; op[1] = o1;
}

// ---------------- attention scores + softmax + gated scatter-add ----------
__global__ void __launch_bounds__(256) attn_scatter_kernel(
    const float* __restrict__ q, const float* __restrict__ k,
    const float* __restrict__ gate, const int* __restrict__ ids,
    const float* __restrict__ mscale, float* __restrict__ logits)
{
    const int row = blockIdx.x;
    const int i = row & (S_LEN - 1);
    const int b = row >> 10;
    if (i == 0) return;  // fully-masked row contributes zero
    __shared__ float qs[MDIM];
    __shared__ float sc[S_LEN];
    __shared__ float red[8];
    const int tid = threadIdx.x;
    if (tid < 32) ((float4*)qs)[tid] = ((const float4*)(q + (size_t)row * MDIM))[tid];
    __syncthreads();

    float lmax = -3.402823466e38f;
    for (int j = tid; j < i; j += 256) {
        const float4* kr = (const float4*)(k + (size_t)(b * S_LEN + j) * MDIM);
        float acc = 0.f;
#pragma unroll
        for (int m = 0; m < 32; m++) {
            float4 kv = kr[m];
            float4 qv = ((const float4*)qs)[m];
            acc += kv.x * qv.x + kv.y * qv.y + kv.z * qv.z + kv.w * qv.w;
        }
        acc *= 0.08838834764831845f;  // 1/sqrt(128)
        sc[j] = acc;
        lmax = fmaxf(lmax, acc);
    }
#pragma unroll
    for (int off = 16; off > 0; off >>= 1)
        lmax = fmaxf(lmax, __shfl_xor_sync(0xffffffffu, lmax, off));
    if ((tid & 31) == 0) red[tid >> 5] = lmax;
    __syncthreads();
    float mx = -3.402823466e38f;
#pragma unroll
    for (int u = 0; u < 8; u++) mx = fmaxf(mx, red[u]);
    __syncthreads();

    float ls = 0.f;
    for (int j = tid; j < i; j += 256) {
        float e = expf(sc[j] - mx);
        sc[j] = e;
        ls += e;
    }
#pragma unroll
    for (int off = 16; off > 0; off >>= 1)
        ls += __shfl_xor_sync(0xffffffffu, ls, off);
    if ((tid & 31) == 0) red[tid >> 5] = ls;
    __syncthreads();
    float tot = 0.f;
#pragma unroll
    for (int u = 0; u < 8; u++) tot += red[u];

    const float coeff = gate[row] * mscale[0] / fmaxf(tot, 1e-6f);
    float* lrow = logits + (size_t)row * VDIM;
    const int* idrow = ids + b * S_LEN;
    for (int j = tid; j < i; j += 256)
        atomicAdd(lrow + idrow[j], sc[j] * coeff);
}

// ---------------- launch ----------------
extern "C" void kernel_launch(void* const* d_in, const int* in_sizes, int n_in,
                              void* d_out, int out_size)
{
    const int*   ids    = (const int*)  d_in[0];
    const float* emb    = (const float*)d_in[1];
    const float* w_ih   = (const float*)d_in[2];
    const float* b_ih   = (const float*)d_in[3];
    const float* w_hh   = (const float*)d_in[4];
    const float* b_hh   = (const float*)d_in[5];
    const float* ln_g   = (const float*)d_in[6];
    const float* ln_b   = (const float*)d_in[7];
    const float* wq     = (const float*)d_in[8];
    const float* bq     = (const float*)d_in[9];
    const float* wk     = (const float*)d_in[10];
    const float* bk     = (const float*)d_in[11];
    const float* wg     = (const float*)d_in[12];
    const float* bg     = (const float*)d_in[13];
    const float* w_fc   = (const float*)d_in[14];
    const float* b_fc   = (const float*)d_in[15];
    const float* w_pr   = (const float*)d_in[16];
    const float* b_pr   = (const float*)d_in[17];
    const float* obias  = (const float*)d_in[18];
    const float* mscale = (const float*)d_in[19];
    float* out = (float*)d_out;

    float *xg, *states, *ns, *hf, *base, *qv, *kv, *gate;
    cudaGetSymbolAddress((void**)&xg,     g_xg);
    cudaGetSymbolAddress((void**)&states, g_states);
    cudaGetSymbolAddress((void**)&ns,     g_ns);
    cudaGetSymbolAddress((void**)&hf,     g_hf);
    cudaGetSymbolAddress((void**)&base,   g_base);
    cudaGetSymbolAddress((void**)&qv,     g_q);
    cudaGetSymbolAddress((void**)&kv,     g_k);
    cudaGetSymbolAddress((void**)&gate,   g_gate);

    // 1) xg = emb[ids] @ w_ih^T + b_ih        (2048 x 3072, K=512)
    sgemm_tn<0, true><<<dim3(24, 16), 256>>>(emb, w_ih, b_ih, xg, 2048, 3072, 512, ids);
    // 2) reset barrier + h0
    init_kernel<<<16, 256>>>();
    // 3) GRU scan (persistent, 128 co-resident CTAs)
    gru_kernel<<<128, 256>>>(xg, w_hh, b_hh, states);
    // 4) LayerNorm + gate
    ln_gate_kernel<<<BATCH * S_LEN, 256>>>(states, ln_g, ln_b, wg, bg, ns, gate);
    // 5) q / k projections
    qk_kernel<<<dim3(128, 2), 256>>>(states, wq, bq, wk, bk, qv, kv);
    // 6) hf = relu(ns @ w_fc^T + b_fc)^2      (2048 x 2048, K=1024)
    sgemm_tn<1, false><<<dim3(16, 16), 256>>>(ns, w_fc, b_fc, hf, 2048, 2048, 1024, nullptr);
    // 7) base = hf @ w_pr^T + b_pr            (2048 x 512, K=2048)
    sgemm_tn<0, false><<<dim3(4, 16), 256>>>(hf, w_pr, b_pr, base, 2048, 512, 2048, nullptr);
    // 8) logits = base @ emb^T + out_bias     (2048 x 32000, K=512)
    sgemm_tn<0, false><<<dim3(250, 16), 256>>>(base, emb, obias, out, 2048, 32000, 512, nullptr);
    // 9) attention softmax + gated scatter-add into logits
    attn_scatter_kernel<<<BATCH * S_LEN, 256>>>(qv, kv, gate, ids, mscale, out);
}

// round 4
// speedup vs baseline: 1.3662x; 1.3662x over previous
#include <cuda_runtime.h>
#include <cuda_bf16.h>
#include <math.h>
#include <stdint.h>

#define S_LEN 1024
#define BATCH 2
#define HDIM  1024
#define EDIM  512
#define VDIM  32000
#define MDIM  128

// ---------------- scratch (device globals; no allocations) ----------------
__device__ float g_xg[BATCH * S_LEN * 3 * HDIM];
__device__ float g_states[BATCH * S_LEN * HDIM];
__device__ float g_ns[BATCH * S_LEN * HDIM];
__device__ float g_hf[BATCH * S_LEN * 4 * EDIM];
__device__ float g_base[BATCH * S_LEN * EDIM];
__device__ float g_q[BATCH * S_LEN * MDIM];
__device__ float g_k[BATCH * S_LEN * MDIM];
__device__ float g_gate[BATCH * S_LEN];
__device__ float g_hbuf[2 * BATCH * HDIM];
__device__ unsigned int g_bar;

// ---------------- init ----------------
__global__ void init_kernel() {
    int t = blockIdx.x * blockDim.x + threadIdx.x;
    if (t == 0) g_bar = 0u;
    if (t < 2 * BATCH * HDIM) g_hbuf[t] = 0.f;
}

// ================= portable tensor-core helpers (sm_80+ PTX) =================
__device__ __forceinline__ uint32_t smem_u32(const void* p) {
    uint32_t a;
    asm("{ .reg .u64 t; cvta.to.shared.u64 t, %1; cvt.u32.u64 %0, t; }" : "=r"(a) : "l"(p));
    return a;
}

__device__ __forceinline__ void ldsm4(uint32_t* r, uint32_t addr) {
    asm volatile("ldmatrix.sync.aligned.m8n8.x4.shared.b16 {%0,%1,%2,%3}, [%4];"
                 : "=r"(r[0]), "=r"(r[1]), "=r"(r[2]), "=r"(r[3]) : "r"(addr));
}

__device__ __forceinline__ void mma16816(float* d, const uint32_t* a, const uint32_t* b) {
    asm volatile(
        "mma.sync.aligned.m16n8k16.row.col.f32.bf16.bf16.f32 "
        "{%0,%1,%2,%3}, {%4,%5,%6,%7}, {%8,%9}, {%0,%1,%2,%3};"
        : "+f"(d[0]), "+f"(d[1]), "+f"(d[2]), "+f"(d[3])
        : "r"(a[0]), "r"(a[1]), "r"(a[2]), "r"(a[3]), "r"(b[0]), "r"(b[1]));
}

// split fp32 -> (hi, lo) bf16 pairs, 8B each
__device__ __forceinline__ void cvt_split_store(char* hp, char* lp, float4 v) {
    __nv_bfloat162 h01 = __floats2bfloat162_rn(v.x, v.y);
    __nv_bfloat162 h23 = __floats2bfloat162_rn(v.z, v.w);
    float l0 = v.x - __bfloat162float(h01.x);
    float l1 = v.y - __bfloat162float(h01.y);
    float l2 = v.z - __bfloat162float(h23.x);
    float l3 = v.w - __bfloat162float(h23.y);
    __nv_bfloat162 L01 = __floats2bfloat162_rn(l0, l1);
    __nv_bfloat162 L23 = __floats2bfloat162_rn(l2, l3);
    *(uint2*)hp = make_uint2(*(uint32_t*)&h01, *(uint32_t*)&h23);
    *(uint2*)lp = make_uint2(*(uint32_t*)&L01, *(uint32_t*)&L23);
}

// ======== split-bf16 HMMA GEMM: C[M,N] = A[M,K] @ B[N,K]^T + bias ========
// grid = (N/128, M/128), 256 threads (8 warps, 4x2), K % 32 == 0.
// smem rows padded to 80 bytes (40 bf16) -> ldmatrix conflict-free.
#define MT_STRIDE_B 80
#define MT_MAT_B    (128 * MT_STRIDE_B)        // 10240 per matrix
#define MT_BUF_B    (4 * MT_MAT_B)             // Ah, Al, Bh, Bl
#define MT_SMEM_TOTAL (1024 + 2 * MT_BUF_B)    // 82944

template <int EPI, bool GATHER>
__global__ void __launch_bounds__(256, 1) mma_gemm(
    const float* __restrict__ A, const float* __restrict__ Bm,
    const float* __restrict__ bias, float* __restrict__ C,
    int N, int K, const int* __restrict__ gidx)
{
    extern __shared__ __align__(128) char smem[];
    const uint32_t smb = smem_u32(smem);
    const int tid = threadIdx.x;
    const int wid = tid >> 5, lane = tid & 31;
    const int wm = wid & 3, wn = wid >> 2;
    const int m0 = blockIdx.y * 128, n0 = blockIdx.x * 128;
    int* s_ids = (int*)smem;

    if (GATHER && tid < 128) s_ids[tid] = gidx[m0 + tid];
    __syncthreads();

    float d[2][8][4];
#pragma unroll
    for (int i = 0; i < 2; i++)
#pragma unroll
        for (int j = 0; j < 8; j++)
#pragma unroll
            for (int c = 0; c < 4; c++) d[i][j][c] = 0.f;

    const int nc = K >> 5;

    // per-thread loader coords: 4 float4 per matrix per chunk
    // idx = tid + 256*i ; r = idx>>3 ; c4 = (idx&7)*4
    float4 va[4], vb[4];
    {
        const int k0 = 0;
#pragma unroll
        for (int i = 0; i < 4; i++) {
            int idx = tid + 256 * i;
            int r = idx >> 3, c4 = (idx & 7) << 2;
            int arow = GATHER ? s_ids[r] : (m0 + r);
            va[i] = *(const float4*)(A + (size_t)arow * K + k0 + c4);
            vb[i] = *(const float4*)(Bm + (size_t)(n0 + r) * K + k0 + c4);
        }
        char* tA = smem + 1024;
        char* tB = tA + 2 * MT_MAT_B;
#pragma unroll
        for (int i = 0; i < 4; i++) {
            int idx = tid + 256 * i;
            int r = idx >> 3, c4 = (idx & 7) << 2;
            int off = r * MT_STRIDE_B + c4 * 2;
            cvt_split_store(tA + off, tA + MT_MAT_B + off, va[i]);
            cvt_split_store(tB + off, tB + MT_MAT_B + off, vb[i]);
        }
    }
    __syncthreads();

    for (int s = 0; s < nc; s++) {
        // prefetch next chunk from gmem into registers
        if (s + 1 < nc) {
            const int k0 = (s + 1) << 5;
#pragma unroll
            for (int i = 0; i < 4; i++) {
                int idx = tid + 256 * i;
                int r = idx >> 3, c4 = (idx & 7) << 2;
                int arow = GATHER ? s_ids[r] : (m0 + r);
                va[i] = *(const float4*)(A + (size_t)arow * K + k0 + c4);
                vb[i] = *(const float4*)(Bm + (size_t)(n0 + r) * K + k0 + c4);
            }
        }

        const uint32_t bufA = smb + 1024 + (s & 1) * MT_BUF_B;
        const uint32_t bufB = bufA + 2 * MT_MAT_B;
#pragma unroll
        for (int h = 0; h < 2; h++) {     // two k16 halves of the 32-chunk
            const int k16 = h * 16;
            uint32_t ah[2][4], al[2][4], bh[4][4], bl[4][4];
#pragma unroll
            for (int mt = 0; mt < 2; mt++) {
                uint32_t addr = bufA + (wm * 32 + mt * 16 + (lane & 15)) * MT_STRIDE_B
                              + (k16 + (lane >> 4) * 8) * 2;
                ldsm4(ah[mt], addr);
                ldsm4(al[mt], addr + MT_MAT_B);
            }
#pragma unroll
            for (int p = 0; p < 4; p++) {
                int nrow = wn * 64 + p * 16 + (lane & 7) + ((lane >> 4) & 1) * 8;
                int kk = k16 + ((lane >> 3) & 1) * 8;
                uint32_t addr = bufB + nrow * MT_STRIDE_B + kk * 2;
                ldsm4(bh[p], addr);
                ldsm4(bl[p], addr + MT_MAT_B);
            }
#pragma unroll
            for (int mt = 0; mt < 2; mt++)
#pragma unroll
                for (int nt = 0; nt < 8; nt++) {
                    const uint32_t* bhp = &bh[nt >> 1][(nt & 1) * 2];
                    const uint32_t* blp = &bl[nt >> 1][(nt & 1) * 2];
                    mma16816(d[mt][nt], ah[mt], bhp);
                    mma16816(d[mt][nt], ah[mt], blp);
                    mma16816(d[mt][nt], al[mt], bhp);
                }
        }

        if (s + 1 < nc) {
            __syncthreads();
            char* tA = smem + 1024 + ((s + 1) & 1) * MT_BUF_B;
            char* tB = tA + 2 * MT_MAT_B;
#pragma unroll
            for (int i = 0; i < 4; i++) {
                int idx = tid + 256 * i;
                int r = idx >> 3, c4 = (idx & 7) << 2;
                int off = r * MT_STRIDE_B + c4 * 2;
                cvt_split_store(tA + off, tA + MT_MAT_B + off, va[i]);
                cvt_split_store(tB + off, tB + MT_MAT_B + off, vb[i]);
            }
            __syncthreads();
        }
    }

    // epilogue: d frag m16n8: (d0,d1)->row g, cols c,c+1 ; (d2,d3)->row g+8
#pragma unroll
    for (int mt = 0; mt < 2; mt++) {
        const int row = m0 + wm * 32 + mt * 16 + (lane >> 2);
#pragma unroll
        for (int nt = 0; nt < 8; nt++) {
            const int col = n0 + wn * 64 + nt * 8 + (lane & 3) * 2;
            float b0 = bias[col], b1 = bias[col + 1];
            float x0 = d[mt][nt][0] + b0, x1 = d[mt][nt][1] + b1;
            float x2 = d[mt][nt][2] + b0, x3 = d[mt][nt][3] + b1;
            if (EPI == 1) {
                x0 = fmaxf(x0, 0.f); x0 *= x0;
                x1 = fmaxf(x1, 0.f); x1 *= x1;
                x2 = fmaxf(x2, 0.f); x2 *= x2;
                x3 = fmaxf(x3, 0.f); x3 *= x3;
            }
            *(float2*)(C + (size_t)row * N + col)       = make_float2(x0, x1);
            *(float2*)(C + (size_t)(row + 8) * N + col) = make_float2(x2, x3);
        }
    }
}

// ---------------- GRU: persistent, 128 CTAs x 256 thr, weights in regs ----
__global__ void __launch_bounds__(256, 1) gru_kernel(
    const float* __restrict__ xg, const float* __restrict__ w_hh,
    const float* __restrict__ b_hh, float* __restrict__ states)
{
    __shared__ float hsh[2 * HDIM];
    __shared__ float dres[8][3][2];
    __shared__ float bsh[3][8];
    const int tid = threadIdx.x;
    const int w = tid >> 5, l = tid & 31;
    const int jbase = blockIdx.x * 8;

    float4 wreg[3][8];
#pragma unroll
    for (int g = 0; g < 3; g++) {
        const float* wr = w_hh + (size_t)(g * HDIM + jbase + w) * HDIM + l * 4;
#pragma unroll
        for (int u = 0; u < 8; u++)
            wreg[g][u] = *(const float4*)(wr + u * 128);
    }
    if (tid < 24) bsh[tid >> 3][tid & 7] = b_hh[(tid >> 3) * HDIM + jbase + (tid & 7)];

    const unsigned G = gridDim.x;
    for (int t = 0; t < S_LEN; t++) {
        const int p = t & 1;
        {
            const float4* hs = (const float4*)(g_hbuf + p * (2 * HDIM));
            float4* hd = (float4*)hsh;
            hd[tid]       = __ldcg(hs + tid);
            hd[tid + 256] = __ldcg(hs + tid + 256);
        }
        float xr = 0.f, xz = 0.f, xn = 0.f;
        if (tid < 16) {
            const int b = tid >> 3, j2 = tid & 7;
            const float* xp = xg + (size_t)(b * S_LEN + t) * (3 * HDIM) + jbase + j2;
            xr = xp[0]; xz = xp[HDIM]; xn = xp[2 * HDIM];
        }
        __syncthreads();

        float a00 = 0.f, a01 = 0.f, a10 = 0.f, a11 = 0.f, a20 = 0.f, a21 = 0.f;
#pragma unroll
        for (int u = 0; u < 8; u++) {
            float4 h0 = *(const float4*)&hsh[u * 128 + l * 4];
            float4 h1 = *(const float4*)&hsh[HDIM + u * 128 + l * 4];
            float4 w0 = wreg[0][u], w1 = wreg[1][u], w2 = wreg[2][u];
            a00 += w0.x * h0.x + w0.y * h0.y + w0.z * h0.z + w0.w * h0.w;
            a01 += w0.x * h1.x + w0.y * h1.y + w0.z * h1.z + w0.w * h1.w;
            a10 += w1.x * h0.x + w1.y * h0.y + w1.z * h0.z + w1.w * h0.w;
            a11 += w1.x * h1.x + w1.y * h1.y + w1.z * h1.z + w1.w * h1.w;
            a20 += w2.x * h0.x + w2.y * h0.y + w2.z * h0.z + w2.w * h0.w;
            a21 += w2.x * h1.x + w2.y * h1.y + w2.z * h1.z + w2.w * h1.w;
        }
#pragma unroll
        for (int off = 16; off > 0; off >>= 1) {
            a00 += __shfl_xor_sync(0xffffffffu, a00, off);
            a01 += __shfl_xor_sync(0xffffffffu, a01, off);
            a10 += __shfl_xor_sync(0xffffffffu, a10, off);
            a11 += __shfl_xor_sync(0xffffffffu, a11, off);
            a20 += __shfl_xor_sync(0xffffffffu, a20, off);
            a21 += __shfl_xor_sync(0xffffffffu, a21, off);
        }
        if (l == 0) {
            dres[w][0][0] = a00; dres[w][0][1] = a01;
            dres[w][1][0] = a10; dres[w][1][1] = a11;
            dres[w][2][0] = a20; dres[w][2][1] = a21;
        }
        __syncthreads();

        if (tid < 16) {
            const int b = tid >> 3, j2 = tid & 7;
            float hr = dres[j2][0][b] + bsh[0][j2];
            float hz = dres[j2][1][b] + bsh[1][j2];
            float hn = dres[j2][2][b] + bsh[2][j2];
            float r = 1.f / (1.f + expf(-(xr + hr)));
            float z = 1.f / (1.f + expf(-(xz + hz)));
            float n = tanhf(xn + r * hn);
            float hold = hsh[b * HDIM + jbase + j2];
            float hnew = (1.f - z) * n + z * hold;
            __stcg(&g_hbuf[(p ^ 1) * (2 * HDIM) + b * HDIM + jbase + j2], hnew);
            states[(size_t)(b * S_LEN + t) * HDIM + jbase + j2] = hnew;
        }
        __syncthreads();

        if (tid == 0) {
            __threadfence();
            atomicAdd(&g_bar, 1u);
            const unsigned target = (unsigned)(t + 1) * G;
            while (*((volatile unsigned*)&g_bar) < target) { }
            __threadfence();
        }
        __syncthreads();
    }
}

// ---------------- LayerNorm + gate ----------------
__global__ void __launch_bounds__(256) ln_gate_kernel(
    const float* __restrict__ states, const float* __restrict__ ln_g,
    const float* __restrict__ ln_b, const float* __restrict__ wg,
    const float* __restrict__ bg, float* __restrict__ ns, float* __restrict__ gate)
{
    __shared__ float red[3][8];
    const int row = blockIdx.x;
    const int tid = threadIdx.x;
    const float4 xv = ((const float4*)(states + (size_t)row * HDIM))[tid];
    const float4 wv = ((const float4*)wg)[tid];
    float s  = xv.x + xv.y + xv.z + xv.w;
    float sq = xv.x * xv.x + xv.y * xv.y + xv.z * xv.z + xv.w * xv.w;
    float wd = xv.x * wv.x + xv.y * wv.y + xv.z * wv.z + xv.w * wv.w;
#pragma unroll
    for (int off = 16; off > 0; off >>= 1) {
        s  += __shfl_xor_sync(0xffffffffu, s,  off);
        sq += __shfl_xor_sync(0xffffffffu, sq, off);
        wd += __shfl_xor_sync(0xffffffffu, wd, off);
    }
    if ((tid & 31) == 0) { red[0][tid >> 5] = s; red[1][tid >> 5] = sq; red[2][tid >> 5] = wd; }
    __syncthreads();
    s = 0.f; sq = 0.f; wd = 0.f;
#pragma unroll
    for (int u = 0; u < 8; u++) { s += red[0][u]; sq += red[1][u]; wd += red[2][u]; }
    const float mu = s * (1.f / HDIM);
    const float var = sq * (1.f / HDIM) - mu * mu;
    const float rstd = rsqrtf(var + 1e-5f);
    const float4 gv = ((const float4*)ln_g)[tid];
    const float4 bv = ((const float4*)ln_b)[tid];
    float4 o;
    o.x = (xv.x - mu) * rstd * gv.x + bv.x;
    o.y = (xv.y - mu) * rstd * gv.y + bv.y;
    o.z = (xv.z - mu) * rstd * gv.z + bv.z;
    o.w = (xv.w - mu) * rstd * gv.w + bv.w;
    ((float4*)(ns + (size_t)row * HDIM))[tid] = o;
    if (tid == 0) gate[row] = 1.f / (1.f + expf(-(wd + bg[0])));
}

// ---------------- q/k projection ----------------
__global__ void __launch_bounds__(256) qk_kernel(
    const float* __restrict__ states,
    const float* __restrict__ wq, const float* __restrict__ bq,
    const float* __restrict__ wk, const float* __restrict__ bk,
    float* __restrict__ qout, float* __restrict__ kout)
{
    const float* W    = blockIdx.y ? wk : wq;
    const float* bias = blockIdx.y ? bk : bq;
    float* out        = blockIdx.y ? kout : qout;
    __shared__ float As[16][20];
    __shared__ float Ws[16][128];
    const int tid = threadIdx.x;
    const int m0 = blockIdx.x * 16;
    const int tm = tid >> 4;
    const int tn0 = (tid & 15) * 8;
    float acc[8] = {0.f, 0.f, 0.f, 0.f, 0.f, 0.f, 0.f, 0.f};

    for (int k0 = 0; k0 < HDIM; k0 += 16) {
        {
            const int n = tid >> 1;
            const int ks = (tid & 1) * 8;
            const float* wp = W + (size_t)n * HDIM + k0 + ks;
            float4 w0 = *(const float4*)wp;
            float4 w1 = *(const float4*)(wp + 4);
            Ws[ks + 0][n] = w0.x; Ws[ks + 1][n] = w0.y; Ws[ks + 2][n] = w0.z; Ws[ks + 3][n] = w0.w;
            Ws[ks + 4][n] = w1.x; Ws[ks + 5][n] = w1.y; Ws[ks + 6][n] = w1.z; Ws[ks + 7][n] = w1.w;
        }
        if (tid < 64) {
            const int m = tid >> 2;
            const int ks = (tid & 3) * 4;
            float4 a = *(const float4*)(states + (size_t)(m0 + m) * HDIM + k0 + ks);
            As[m][ks] = a.x; As[m][ks + 1] = a.y; As[m][ks + 2] = a.z; As[m][ks + 3] = a.w;
        }
        __syncthreads();
#pragma unroll
        for (int kk = 0; kk < 16; kk++) {
            float a = As[tm][kk];
            float4 b0 = *(const float4*)&Ws[kk][tn0];
            float4 b1 = *(const float4*)&Ws[kk][tn0 + 4];
            acc[0] += a * b0.x; acc[1] += a * b0.y; acc[2] += a * b0.z; acc[3] += a * b0.w;
            acc[4] += a * b1.x; acc[5] += a * b1.y; acc[6] += a * b1.z; acc[7] += a * b1.w;
        }
        __syncthreads();
    }
    float4 o0 = make_float4(acc[0] + bias[tn0 + 0], acc[1] + bias[tn0 + 1],
                            acc[2] + bias[tn0 + 2], acc[3] + bias[tn0 + 3]);
    float4 o1 = make_float4(acc[4] + bias[tn0 + 4], acc[5] + bias[tn0 + 5],
                            acc[6] + bias[tn0 + 6], acc[7] + bias[tn0 + 7]);
    float4* op = (float4*)(out + (size_t)(m0 + tm) * MDIM + tn0);
    op[0] = o0; op[1] = o1;
}

// ---------------- attention scores + softmax + gated scatter-add ----------
__global__ void __launch_bounds__(256) attn_scatter_kernel(
    const float* __restrict__ q, const float* __restrict__ k,
    const float* __restrict__ gate, const int* __restrict__ ids,
    const float* __restrict__ mscale, float* __restrict__ logits)
{
    const int row = blockIdx.x;
    const int i = row & (S_LEN - 1);
    const int b = row >> 10;
    if (i == 0) return;
    __shared__ float qs[MDIM];
    __shared__ float sc[S_LEN];
    __shared__ float red[8];
    const int tid = threadIdx.x;
    if (tid < 32) ((float4*)qs)[tid] = ((const float4*)(q + (size_t)row * MDIM))[tid];
    __syncthreads();

    float lmax = -3.402823466e38f;
    for (int j = tid; j < i; j += 256) {
        const float4* kr = (const float4*)(k + (size_t)(b * S_LEN + j) * MDIM);
        float acc = 0.f;
#pragma unroll
        for (int m = 0; m < 32; m++) {
            float4 kv = kr[m];
            float4 qv = ((const float4*)qs)[m];
            acc += kv.x * qv.x + kv.y * qv.y + kv.z * qv.z + kv.w * qv.w;
        }
        acc *= 0.08838834764831845f;
        sc[j] = acc;
        lmax = fmaxf(lmax, acc);
    }
#pragma unroll
    for (int off = 16; off > 0; off >>= 1)
        lmax = fmaxf(lmax, __shfl_xor_sync(0xffffffffu, lmax, off));
    if ((tid & 31) == 0) red[tid >> 5] = lmax;
    __syncthreads();
    float mx = -3.402823466e38f;
#pragma unroll
    for (int u = 0; u < 8; u++) mx = fmaxf(mx, red[u]);
    __syncthreads();

    float ls = 0.f;
    for (int j = tid; j < i; j += 256) {
        float e = expf(sc[j] - mx);
        sc[j] = e;
        ls += e;
    }
#pragma unroll
    for (int off = 16; off > 0; off >>= 1)
        ls += __shfl_xor_sync(0xffffffffu, ls, off);
    if ((tid & 31) == 0) red[tid >> 5] = ls;
    __syncthreads();
    float tot = 0.f;
#pragma unroll
    for (int u = 0; u < 8; u++) tot += red[u];

    const float coeff = gate[row] * mscale[0] / fmaxf(tot, 1e-6f);
    float* lrow = logits + (size_t)row * VDIM;
    const int* idrow = ids + b * S_LEN;
    for (int j = tid; j < i; j += 256)
        atomicAdd(lrow + idrow[j], sc[j] * coeff);
}

// ---------------- launch ----------------
extern "C" void kernel_launch(void* const* d_in, const int* in_sizes, int n_in,
                              void* d_out, int out_size)
{
    const int*   ids    = (const int*)  d_in[0];
    const float* emb    = (const float*)d_in[1];
    const float* w_ih   = (const float*)d_in[2];
    const float* b_ih   = (const float*)d_in[3];
    const float* w_hh   = (const float*)d_in[4];
    const float* b_hh   = (const float*)d_in[5];
    const float* ln_g   = (const float*)d_in[6];
    const float* ln_b   = (const float*)d_in[7];
    const float* wq     = (const float*)d_in[8];
    const float* bq     = (const float*)d_in[9];
    const float* wk     = (const float*)d_in[10];
    const float* bk     = (const float*)d_in[11];
    const float* wg     = (const float*)d_in[12];
    const float* bg     = (const float*)d_in[13];
    const float* w_fc   = (const float*)d_in[14];
    const float* b_fc   = (const float*)d_in[15];
    const float* w_pr   = (const float*)d_in[16];
    const float* b_pr   = (const float*)d_in[17];
    const float* obias  = (const float*)d_in[18];
    const float* mscale = (const float*)d_in[19];
    float* out = (float*)d_out;

    float *xg, *states, *ns, *hf, *base, *qv, *kv, *gate;
    cudaGetSymbolAddress((void**)&xg,     g_xg);
    cudaGetSymbolAddress((void**)&states, g_states);
    cudaGetSymbolAddress((void**)&ns,     g_ns);
    cudaGetSymbolAddress((void**)&hf,     g_hf);
    cudaGetSymbolAddress((void**)&base,   g_base);
    cudaGetSymbolAddress((void**)&qv,     g_q);
    cudaGetSymbolAddress((void**)&kv,     g_k);
    cudaGetSymbolAddress((void**)&gate,   g_gate);

    cudaFuncSetAttribute(mma_gemm<0, true>,  cudaFuncAttributeMaxDynamicSharedMemorySize, MT_SMEM_TOTAL);
    cudaFuncSetAttribute(mma_gemm<0, false>, cudaFuncAttributeMaxDynamicSharedMemorySize, MT_SMEM_TOTAL);
    cudaFuncSetAttribute(mma_gemm<1, false>, cudaFuncAttributeMaxDynamicSharedMemorySize, MT_SMEM_TOTAL);

    // 1) xg = emb[ids] @ w_ih^T + b_ih        (2048 x 3072, K=512)
    mma_gemm<0, true><<<dim3(24, 16), 256, MT_SMEM_TOTAL>>>(emb, w_ih, b_ih, xg, 3072, 512, ids);
    // 2) reset barrier + h0
    init_kernel<<<16, 256>>>();
    // 3) GRU scan
    gru_kernel<<<128, 256>>>(xg, w_hh, b_hh, states);
    // 4) LayerNorm + gate
    ln_gate_kernel<<<BATCH * S_LEN, 256>>>(states, ln_g, ln_b, wg, bg, ns, gate);
    // 5) q / k projections
    qk_kernel<<<dim3(128, 2), 256>>>(states, wq, bq, wk, bk, qv, kv);
    // 6) hf = relu(ns @ w_fc^T + b_fc)^2      (2048 x 2048, K=1024)
    mma_gemm<1, false><<<dim3(16, 16), 256, MT_SMEM_TOTAL>>>(ns, w_fc, b_fc, hf, 2048, 1024, nullptr);
    // 7) base = hf @ w_pr^T + b_pr            (2048 x 512, K=2048)
    mma_gemm<0, false><<<dim3(4, 16), 256, MT_SMEM_TOTAL>>>(hf, w_pr, b_pr, base, 512, 2048, nullptr);
    // 8) logits = base @ emb^T + out_bias     (2048 x 32000, K=512)
    mma_gemm<0, false><<<dim3(250, 16), 256, MT_SMEM_TOTAL>>>(base, emb, obias, out, 32000, 512, nullptr);
    // 9) attention softmax + gated scatter-add
    attn_scatter_kernel<<<BATCH * S_LEN, 256>>>(qv, kv, gate, ids, mscale, out);
}